// round 14
// baseline (speedup 1.0000x reference)
#include <cuda_runtime.h>
#include <cuda_bf16.h>
#include <cuda_fp16.h>
#include <cstdint>

// Shapes: x[16,64,64,512], La[16,512,512], W[64,192]; out[16,64,64,512]
#define BELEM 2097152            // 64*64*512 per batch (row=o*64+t, col=n)
#define LAELEM 262144            // 512*512

typedef unsigned short u16;
typedef unsigned int u32;

__device__ __align__(16) float g_U1[(size_t)16 * BELEM];
__device__ __align__(16) u16   g_U2h[(size_t)16 * BELEM];   // fp16 hi
__device__ __align__(16) u16   g_U2l[(size_t)16 * BELEM];   // fp16 lo
__device__ __align__(16) u16   g_Ph [(size_t)16 * BELEM];   // fp16 hi
__device__ __align__(16) u16   g_Pl [(size_t)16 * BELEM];   // fp16 lo
__device__ __align__(16) u16   g_Laf[(size_t)16 * LAELEM];  // fp16 single
__device__ __align__(16) u16   g_Wsh[192 * 64];             // bf16 hi (mix)
__device__ __align__(16) u16   g_Wsl[192 * 64];             // bf16 lo (mix)

// ---------------------------------------------------------------------------
__device__ __forceinline__ u32 s2u(const void* p) {
    u32 a;
    asm("{ .reg .u64 t; cvta.to.shared.u64 t, %1; cvt.u32.u64 %0, t; }" : "=r"(a) : "l"(p));
    return a;
}
__device__ __forceinline__ u32 swz(int row, int kb) {       // 128B rows
    return (u32)(row * 128 + (kb ^ ((row & 7) << 4)));
}
__device__ __forceinline__ u32 swzB(int row, int kb) {      // 64B rows (2-way ok)
    return (u32)(row * 64 + (kb ^ ((row & 3) << 4)));
}
__device__ __forceinline__ void cpa(u32 s, const void* g) {
    asm volatile("cp.async.cg.shared.global [%0], [%1], 16;" :: "r"(s), "l"(g));
}
__device__ __forceinline__ void cpcommit() {
    asm volatile("cp.async.commit_group;" ::: "memory");
}
template<int N> __device__ __forceinline__ void cpwait() {
    asm volatile("cp.async.wait_group %0;" :: "n"(N) : "memory");
}
__device__ __forceinline__ void ldsm4(u32* r, u32 a) {
    asm volatile("ldmatrix.sync.aligned.m8n8.x4.shared.b16 {%0,%1,%2,%3}, [%4];"
        : "=r"(r[0]), "=r"(r[1]), "=r"(r[2]), "=r"(r[3]) : "r"(a));
}
__device__ __forceinline__ void mma_bf(float* d, const u32* a, u32 b0, u32 b1) {
    asm volatile("mma.sync.aligned.m16n8k16.row.col.f32.bf16.bf16.f32 "
        "{%0,%1,%2,%3}, {%4,%5,%6,%7}, {%8,%9}, {%0,%1,%2,%3};"
        : "+f"(d[0]), "+f"(d[1]), "+f"(d[2]), "+f"(d[3])
        : "r"(a[0]), "r"(a[1]), "r"(a[2]), "r"(a[3]), "r"(b0), "r"(b1));
}
__device__ __forceinline__ void mma_fp(float* d, const u32* a, u32 b0, u32 b1) {
    asm volatile("mma.sync.aligned.m16n8k16.row.col.f32.f16.f16.f32 "
        "{%0,%1,%2,%3}, {%4,%5,%6,%7}, {%8,%9}, {%0,%1,%2,%3};"
        : "+f"(d[0]), "+f"(d[1]), "+f"(d[2]), "+f"(d[3])
        : "r"(a[0]), "r"(a[1]), "r"(a[2]), "r"(a[3]), "r"(b0), "r"(b1));
}
__device__ __forceinline__ u32 packlo(float lx, float ly) {  // bf16x2 {ly|lx}
    u32 r;
    asm("cvt.rn.bf16x2.f32 %0, %1, %2;" : "=r"(r) : "f"(ly), "f"(lx));
    return r;
}
__device__ __forceinline__ u32 packh2(float lx, float ly) {  // fp16x2 {ly|lx}
    __half h0 = __float2half_rn(lx), h1 = __float2half_rn(ly);
    return ((u32)__half_as_ushort(h1) << 16) | __half_as_ushort(h0);
}
// fp16 hi/lo split store: hi = RN fp16, lo = RN fp16 of residual
__device__ __forceinline__ void store_hl16(u16* H, u16* L, size_t off, float v0, float v1) {
    __half h0 = __float2half_rn(v0), h1 = __float2half_rn(v1);
    *(u32*)(H + off) = ((u32)__half_as_ushort(h1) << 16) | __half_as_ushort(h0);
    float r0 = v0 - __half2float(h0);
    float r1 = v1 - __half2float(h1);
    *(u32*)(L + off) = packh2(r0, r1);
}

// ---------------------------------------------------------------------------
// k_prep: La fp32 -> fp16 single
// ---------------------------------------------------------------------------
__global__ void k_prep(const float* __restrict__ La) {
    int i = blockIdx.x * blockDim.x + threadIdx.x;   // float4 index
    float4 v = __ldg((const float4*)La + i);
    uint2 h = { packh2(v.x, v.y), packh2(v.z, v.w) };
    ((uint2*)g_Laf)[i] = h;
}

__global__ void k_wstk(const float* __restrict__ W) {
    int i = blockIdx.x * blockDim.x + threadIdx.x;
    if (i >= 192 * 64) return;
    int r = i >> 6, c = i & 63;
    int o = r & 63, reg = r >> 6;
    float v = (reg == 0) ? W[o * 192 + 3 * c + 1]
            : (reg == 1) ? 2.0f * W[o * 192 + 3 * c + 2]
            : W[o * 192 + 3 * c] - W[o * 192 + 3 * c + 2];
    u32 u = __float_as_uint(v);
    g_Wsh[i] = (u16)(u >> 16);
    float res = v - __uint_as_float(u & 0xFFFF0000u);
    __nv_bfloat16 rb = __float2bfloat16(res);
    g_Wsl[i] = *(u16*)&rb;
}

// ---------------------------------------------------------------------------
// k_mix (512 thr, 3xbf16 core, double-buffered staging): per (b,t):
// A=Wstk[192][64] h/l bf16, B=X^T [128 n][64 c] h/l bf16.
// Rows 0-63 -> U1 fp32, 64-127 -> U2 fp16 h/l, 128-191 -> out fp32.
// smem: Wh 0 (24K), Wl 24576; buf k at 49152+k*65536:
//       Bh +0 (16K), Bl +16384, stage +32768 (32K fp32). total 180224
// ---------------------------------------------------------------------------
__global__ __launch_bounds__(512, 1)
void k_mix(const float* __restrict__ x, float* __restrict__ out) {
    extern __shared__ char sm[];
    int tid = threadIdx.x, w = tid >> 5, l = tid & 31;
    int b = blockIdx.x >> 6, t = blockIdx.x & 63;
    u32 su = s2u(sm);
    const float* xb = x + (size_t)b * BELEM + (size_t)t * 512;

    #pragma unroll
    for (int it = 0; it < 6; it++) {               // W: 3072 16B chunks
        int idx = it * 512 + tid;
        int half = idx >= 1536;
        int rem = idx - half * 1536;
        int r = rem >> 3, c = rem & 7;
        const u16* g = (half ? g_Wsl : g_Wsh) + r * 64 + c * 8;
        cpa(su + half * 24576 + swz(r, c * 16), g);
    }
    cpcommit();

    #pragma unroll
    for (int it = 0; it < 4; it++) {               // stage chunk 0
        int idx = it * 512 + tid;
        int c = idx >> 5, q = idx & 31;
        cpa(su + 49152 + 32768 + (u32)(c * 512 + q * 16), xb + (size_t)c * 32768 + q * 4);
    }
    cpcommit();

    int wm = (w >> 2) * 48, wn = (w & 3) * 32;
    int rA = ((l >> 3) & 1) * 8 + (l & 7);
    int ksel = ((l >> 4) & 1) * 16;

    for (int nc = 0; nc < 4; nc++) {
        u32 bo = su + 49152 + (u32)(nc & 1) * 65536;
        if (nc < 3) {
            u32 bn = su + 49152 + (u32)((nc + 1) & 1) * 65536;
            int n1 = (nc + 1) * 128;
            #pragma unroll
            for (int it = 0; it < 4; it++) {
                int idx = it * 512 + tid;
                int c = idx >> 5, q = idx & 31;
                cpa(bn + 32768 + (u32)(c * 512 + q * 16),
                    xb + (size_t)c * 32768 + n1 + q * 4);
            }
            cpcommit();
            cpwait<1>();
        } else {
            cpwait<0>();
        }
        __syncthreads();
        float* stage = (float*)(sm + (bo - su) + 32768);
        #pragma unroll
        for (int it = 0; it < 8; it++) {           // transpose+convert -> B [n][c]
            int idx = it * 512 + tid;
            int cp2 = idx >> 7, n = idx & 127;
            float a0 = stage[(cp2 * 2) * 128 + n];
            float a1 = stage[(cp2 * 2 + 1) * 128 + n];
            u32 u0 = __float_as_uint(a0), u1 = __float_as_uint(a1);
            u32 off = swz(n, cp2 * 4);
            *(u32*)(sm + (bo - su) + off) = __byte_perm(u0, u1, 0x7632);
            *(u32*)(sm + (bo - su) + 16384 + off) =
                packlo(a0 - __uint_as_float(u0 & 0xFFFF0000u),
                       a1 - __uint_as_float(u1 & 0xFFFF0000u));
        }
        __syncthreads();

        float acc[3][4][4];
        #pragma unroll
        for (int mi = 0; mi < 3; mi++)
            #pragma unroll
            for (int ni = 0; ni < 4; ni++)
                #pragma unroll
                for (int j = 0; j < 4; j++) acc[mi][ni][j] = 0.0f;

        #pragma unroll
        for (int s = 0; s < 4; s++) {
            int kb = s * 32 + ksel;
            u32 ah[3][4], al[3][4];
            #pragma unroll
            for (int mi = 0; mi < 3; mi++) {
                ldsm4(ah[mi], su + swz(wm + mi * 16 + rA, kb));
                ldsm4(al[mi], su + 24576 + swz(wm + mi * 16 + rA, kb));
            }
            #pragma unroll
            for (int g4 = 0; g4 < 2; g4++) {
                u32 bh[4], bl[4];
                ldsm4(bh, bo + swz(wn + g4 * 16 + rA, kb));
                ldsm4(bl, bo + 16384 + swz(wn + g4 * 16 + rA, kb));
                #pragma unroll
                for (int mi = 0; mi < 3; mi++)
                    #pragma unroll
                    for (int o = 0; o < 2; o++) {
                        int ni = g4 * 2 + o;
                        mma_bf(acc[mi][ni], ah[mi], bh[o], bh[o + 2]);
                        mma_bf(acc[mi][ni], al[mi], bh[o], bh[o + 2]);
                        mma_bf(acc[mi][ni], ah[mi], bl[o], bl[o + 2]);
                    }
            }
        }

        int n0 = nc * 128;
        #pragma unroll
        for (int mi = 0; mi < 3; mi++) {
            int mb = wm + mi * 16;
            int reg = mb >> 6;
            int o = (mb & 63) + (l >> 2);
            size_t base = (size_t)b * BELEM + (size_t)o * 32768 + (size_t)t * 512;
            #pragma unroll
            for (int ni = 0; ni < 4; ni++) {
                int col = n0 + wn + ni * 8 + 2 * (l & 3);
                float* d = acc[mi][ni];
                size_t o0 = base + col, o1 = o0 + (size_t)8 * 32768;
                if (reg == 0) {
                    float2 v0 = { d[0], d[1] }, v1 = { d[2], d[3] };
                    *(float2*)&g_U1[o0] = v0;
                    *(float2*)&g_U1[o1] = v1;
                } else if (reg == 1) {
                    store_hl16(g_U2h, g_U2l, o0, d[0], d[1]);
                    store_hl16(g_U2h, g_U2l, o1, d[2], d[3]);
                } else {
                    float2 v0 = { d[0], d[1] }, v1 = { d[2], d[3] };
                    *(float2*)&out[o0] = v0;
                    *(float2*)&out[o1] = v1;
                }
            }
        }
    }
}

// ---------------------------------------------------------------------------
// k_gemm (256 thr, 2 CTAs/SM, 4-stage, fp16 2-product):
// pass0: P = U1 + U2@La^T; pass1: out += P@La^T. CTA tile 128x128,
// K=512 in 16 chunks of 32. Stage (24KB): A 16KB (128B rows: [hi k32|lo k32]),
// B 8KB (64B rows, fp16 single). 4 stages = 96KB.
// warps: 8 = 2 m-warps (64 rows) x 4 n-warps (32 cols)
// ---------------------------------------------------------------------------
__device__ __forceinline__ void load_chunk(u32 sb, const u16* Ah, const u16* Al,
                                           const u16* Bf, int kc, int tid) {
    int k0 = kc * 32;
    #pragma unroll
    for (int it = 0; it < 6; it++) {
        int idx = it * 256 + tid;
        if (idx < 1024) {                            // A: 128 rows x 8 chunks
            int r = (idx >> 3) & 127, c = idx & 7;
            int lo = c >> 2;
            const u16* g = (lo ? Al : Ah) + (size_t)r * 512 + k0 + (c & 3) * 8;
            cpa(sb + swz(r, c * 16), g);
        } else {                                     // B: 128 rows x 4 chunks
            int rem = idx - 1024;
            int r = rem >> 2, c = rem & 3;
            const u16* g = Bf + (size_t)r * 512 + k0 + c * 8;
            cpa(sb + 16384 + swzB(r, c * 16), g);
        }
    }
    cpcommit();
}

__global__ __launch_bounds__(256, 2)
void k_gemm(float* __restrict__ out, int pass) {
    extern __shared__ char sm[];
    int tid = threadIdx.x, w = tid >> 5, l = tid & 31;
    int blk = blockIdx.x;
    int b = blk >> 7, mt = (blk >> 2) & 31, qt = blk & 3;
    int m0 = mt * 128, q0 = qt * 128;

    const u16* A0 = (pass ? g_Ph : g_U2h) + (size_t)b * BELEM + (size_t)m0 * 512;
    const u16* A1 = (pass ? g_Pl : g_U2l) + (size_t)b * BELEM + (size_t)m0 * 512;
    const u16* Bf = g_Laf + (size_t)b * LAELEM + (size_t)q0 * 512;
    u32 su = s2u(sm);

    load_chunk(su,         A0, A1, Bf, 0, tid);
    load_chunk(su + 24576, A0, A1, Bf, 1, tid);
    load_chunk(su + 49152, A0, A1, Bf, 2, tid);

    float acc[4][4][4];
    #pragma unroll
    for (int mi = 0; mi < 4; mi++)
        #pragma unroll
        for (int ni = 0; ni < 4; ni++)
            #pragma unroll
            for (int j = 0; j < 4; j++) acc[mi][ni][j] = 0.0f;

    int wm = (w >> 2) * 64, wn = (w & 3) * 32;
    int rA = ((l >> 3) & 1) * 8 + (l & 7);
    int ksel = ((l >> 4) & 1) * 16;

    for (int kc = 0; kc < 16; kc++) {
        if (kc <= 13) cpwait<2>();
        else if (kc == 14) cpwait<1>();
        else cpwait<0>();
        __syncthreads();
        if (kc + 3 < 16)
            load_chunk(su + (u32)((kc + 3) & 3) * 24576, A0, A1, Bf, kc + 3, tid);
        u32 sb = su + (u32)(kc & 3) * 24576;
        #pragma unroll
        for (int s = 0; s < 2; s++) {
            int kb = s * 32 + ksel;
            u32 ah[4][4], al[4][4];
            #pragma unroll
            for (int mi = 0; mi < 4; mi++) {
                ldsm4(ah[mi], sb + swz(wm + mi * 16 + rA, kb));
                ldsm4(al[mi], sb + swz(wm + mi * 16 + rA, kb + 64));
            }
            #pragma unroll
            for (int g4 = 0; g4 < 2; g4++) {
                u32 bh[4];
                ldsm4(bh, sb + 16384 + swzB(wn + g4 * 16 + rA, kb));
                #pragma unroll
                for (int mi = 0; mi < 4; mi++)
                    #pragma unroll
                    for (int o = 0; o < 2; o++) {
                        int ni = g4 * 2 + o;
                        mma_fp(acc[mi][ni], ah[mi], bh[o], bh[o + 2]);
                        mma_fp(acc[mi][ni], al[mi], bh[o], bh[o + 2]);
                    }
            }
        }
    }

    #pragma unroll
    for (int mi = 0; mi < 4; mi++)
        #pragma unroll
        for (int ni = 0; ni < 4; ni++) {
            int row = m0 + wm + mi * 16 + (l >> 2);
            int col = q0 + wn + ni * 8 + 2 * (l & 3);
            size_t o0 = (size_t)b * BELEM + (size_t)row * 512 + col;
            size_t o1 = o0 + 8 * 512;
            float* d = acc[mi][ni];
            if (pass == 0) {
                float2 c0 = *(const float2*)&g_U1[o0];
                float2 c1 = *(const float2*)&g_U1[o1];
                store_hl16(g_Ph, g_Pl, o0, d[0] + c0.x, d[1] + c0.y);
                store_hl16(g_Ph, g_Pl, o1, d[2] + c1.x, d[3] + c1.y);
            } else {
                float2 c0 = *(const float2*)&out[o0];
                float2 c1 = *(const float2*)&out[o1];
                float2 v0 = { d[0] + c0.x, d[1] + c0.y };
                float2 v1 = { d[2] + c1.x, d[3] + c1.y };
                *(float2*)&out[o0] = v0;
                *(float2*)&out[o1] = v1;
            }
        }
}

// ---------------------------------------------------------------------------
extern "C" void kernel_launch(void* const* d_in, const int* in_sizes, int n_in,
                              void* d_out, int out_size) {
    const float* x  = (const float*)d_in[0];
    const float* La = (const float*)d_in[1];
    const float* W  = (const float*)d_in[2];
    float* out = (float*)d_out;
    (void)in_sizes; (void)n_in; (void)out_size;

    cudaFuncSetAttribute(k_mix,  cudaFuncAttributeMaxDynamicSharedMemorySize, 180224);
    cudaFuncSetAttribute(k_gemm, cudaFuncAttributeMaxDynamicSharedMemorySize, 98304);

    k_prep<<<4096, 256>>>(La);
    k_wstk<<<48, 256>>>(W);
    k_mix<<<1024, 512, 180224>>>(x, out);
    k_gemm<<<2048, 256, 98304>>>(out, 0);
    k_gemm<<<2048, 256, 98304>>>(out, 1);
}

// round 16
// speedup vs baseline: 1.1267x; 1.1267x over previous
#include <cuda_runtime.h>
#include <cuda_bf16.h>
#include <cstdint>

// Shapes: x[16,64,64,512], La[16,512,512], W[64,192]; out[16,64,64,512]
#define BELEM 2097152            // 64*64*512 per batch (row=o*64+t, col=n)
#define LAELEM 262144            // 512*512
#define UOFF  ((size_t)16 * BELEM)    // A half-stride (U1 -> U2)
#define BOFF2 ((size_t)16 * LAELEM)   // B half-stride (La -> La2)

typedef unsigned short u16;
typedef unsigned int u32;

// A = [U1 | U2] bf16 hi/lo, B = [La | La2] bf16 hi/lo
__device__ __align__(16) u16 g_Ah[(size_t)2 * 16 * BELEM];
__device__ __align__(16) u16 g_Al[(size_t)2 * 16 * BELEM];
__device__ __align__(16) u16 g_Bh[(size_t)2 * 16 * LAELEM];
__device__ __align__(16) u16 g_Bl[(size_t)2 * 16 * LAELEM];
__device__ __align__(16) u16 g_LaTh[(size_t)16 * LAELEM];
__device__ __align__(16) u16 g_LaTl[(size_t)16 * LAELEM];
__device__ __align__(16) u16 g_Wsh[192 * 64];
__device__ __align__(16) u16 g_Wsl[192 * 64];

// ---------------------------------------------------------------------------
__device__ __forceinline__ u32 s2u(const void* p) {
    u32 a;
    asm("{ .reg .u64 t; cvta.to.shared.u64 t, %1; cvt.u32.u64 %0, t; }" : "=r"(a) : "l"(p));
    return a;
}
__device__ __forceinline__ u32 swz(int row, int kb) {       // 128B rows
    return (u32)(row * 128 + (kb ^ ((row & 7) << 4)));
}
__device__ __forceinline__ void cpa(u32 s, const void* g) {
    asm volatile("cp.async.cg.shared.global [%0], [%1], 16;" :: "r"(s), "l"(g));
}
__device__ __forceinline__ void cpcommit() {
    asm volatile("cp.async.commit_group;" ::: "memory");
}
template<int N> __device__ __forceinline__ void cpwait() {
    asm volatile("cp.async.wait_group %0;" :: "n"(N) : "memory");
}
__device__ __forceinline__ void ldsm4(u32* r, u32 a) {
    asm volatile("ldmatrix.sync.aligned.m8n8.x4.shared.b16 {%0,%1,%2,%3}, [%4];"
        : "=r"(r[0]), "=r"(r[1]), "=r"(r[2]), "=r"(r[3]) : "r"(a));
}
__device__ __forceinline__ void mma_bf(float* d, const u32* a, u32 b0, u32 b1) {
    asm volatile("mma.sync.aligned.m16n8k16.row.col.f32.bf16.bf16.f32 "
        "{%0,%1,%2,%3}, {%4,%5,%6,%7}, {%8,%9}, {%0,%1,%2,%3};"
        : "+f"(d[0]), "+f"(d[1]), "+f"(d[2]), "+f"(d[3])
        : "r"(a[0]), "r"(a[1]), "r"(a[2]), "r"(a[3]), "r"(b0), "r"(b1));
}
__device__ __forceinline__ u32 packlo(float lx, float ly) {  // bf16x2 {ly|lx}
    u32 r;
    asm("cvt.rn.bf16x2.f32 %0, %1, %2;" : "=r"(r) : "f"(ly), "f"(lx));
    return r;
}
// bf16 hi/lo split store: hi = exact truncation, lo = RN residual
__device__ __forceinline__ void store_hl(u16* H, u16* L, size_t off, float v0, float v1) {
    u32 b0 = __float_as_uint(v0), b1 = __float_as_uint(v1);
    *(u32*)(H + off) = __byte_perm(b0, b1, 0x7632);
    float r0 = v0 - __uint_as_float(b0 & 0xFFFF0000u);
    float r1 = v1 - __uint_as_float(b1 & 0xFFFF0000u);
    *(u32*)(L + off) = packlo(r0, r1);
}

// ---------------------------------------------------------------------------
// k_prep: La fp32 -> bf16 hi/lo into B-array half 0
// ---------------------------------------------------------------------------
__global__ void k_prep(const float* __restrict__ La) {
    int i = blockIdx.x * blockDim.x + threadIdx.x;   // float4 index, 1048576
    float4 v = __ldg((const float4*)La + i);
    u32 bx = __float_as_uint(v.x), by = __float_as_uint(v.y);
    u32 bz = __float_as_uint(v.z), bw = __float_as_uint(v.w);
    uint2 h = { __byte_perm(bx, by, 0x7632), __byte_perm(bz, bw, 0x7632) };
    uint2 l = { packlo(v.x - __uint_as_float(bx & 0xFFFF0000u),
                       v.y - __uint_as_float(by & 0xFFFF0000u)),
                packlo(v.z - __uint_as_float(bz & 0xFFFF0000u),
                       v.w - __uint_as_float(bw & 0xFFFF0000u)) };
    ((uint2*)g_Bh)[i] = h;
    ((uint2*)g_Bl)[i] = l;
}

// ---------------------------------------------------------------------------
// k_trans: g_LaT[b][j][k] = La[b][k][j]  (bf16 hi/lo), 32x32 smem tiles
// ---------------------------------------------------------------------------
__global__ void k_trans(const float* __restrict__ La) {
    __shared__ float s[32][33];
    int b = blockIdx.z, k0 = blockIdx.y * 32, j0 = blockIdx.x * 32;
    int tx = threadIdx.x, ty = threadIdx.y;          // (32, 8)
    const float* src = La + (size_t)b * LAELEM;
    #pragma unroll
    for (int w = 0; w < 4; w++)
        s[ty + 8 * w][tx] = src[(size_t)(k0 + ty + 8 * w) * 512 + j0 + tx];
    __syncthreads();
    #pragma unroll
    for (int w = 0; w < 4; w++) {
        float v = s[tx][ty + 8 * w];
        u32 u = __float_as_uint(v);
        size_t o = (size_t)b * LAELEM + (size_t)(j0 + ty + 8 * w) * 512 + k0 + tx;
        g_LaTh[o] = (u16)(u >> 16);
        __nv_bfloat16 rb = __float2bfloat16(v - __uint_as_float(u & 0xFFFF0000u));
        g_LaTl[o] = *(u16*)&rb;
    }
}

// ---------------------------------------------------------------------------
// k_wstk: folded weights -> bf16 hi/lo. rows: 0-63 W1, 64-127 2*W2, 128-191 W0-W2
// ---------------------------------------------------------------------------
__global__ void k_wstk(const float* __restrict__ W) {
    int i = blockIdx.x * blockDim.x + threadIdx.x;
    if (i >= 192 * 64) return;
    int r = i >> 6, c = i & 63;
    int o = r & 63, reg = r >> 6;
    float v = (reg == 0) ? W[o * 192 + 3 * c + 1]
            : (reg == 1) ? 2.0f * W[o * 192 + 3 * c + 2]
            : W[o * 192 + 3 * c] - W[o * 192 + 3 * c + 2];
    u32 u = __float_as_uint(v);
    g_Wsh[i] = (u16)(u >> 16);
    float res = v - __uint_as_float(u & 0xFFFF0000u);
    __nv_bfloat16 rb = __float2bfloat16(res);
    g_Wsl[i] = *(u16*)&rb;
}

// ---------------------------------------------------------------------------
// k_mix (512 thr, 3xbf16, double-buffered staging): per (b,t):
// Rows 0-63 -> U1 (bf16 hl -> A half0), 64-127 -> U2 (A half1), 128-191 -> out fp32.
// smem: Wh 0 (24K), Wl 24576; buf k at 49152+k*65536:
//       Bh +0 (16K), Bl +16384, stage +32768 (32K fp32). total 180224
// ---------------------------------------------------------------------------
__global__ __launch_bounds__(512, 1)
void k_mix(const float* __restrict__ x, float* __restrict__ out) {
    extern __shared__ char sm[];
    int tid = threadIdx.x, w = tid >> 5, l = tid & 31;
    int b = blockIdx.x >> 6, t = blockIdx.x & 63;
    u32 su = s2u(sm);
    const float* xb = x + (size_t)b * BELEM + (size_t)t * 512;

    #pragma unroll
    for (int it = 0; it < 6; it++) {               // W: 3072 16B chunks
        int idx = it * 512 + tid;
        int half = idx >= 1536;
        int rem = idx - half * 1536;
        int r = rem >> 3, c = rem & 7;
        const u16* g = (half ? g_Wsl : g_Wsh) + r * 64 + c * 8;
        cpa(su + half * 24576 + swz(r, c * 16), g);
    }
    cpcommit();

    #pragma unroll
    for (int it = 0; it < 4; it++) {               // stage chunk 0
        int idx = it * 512 + tid;
        int c = idx >> 5, q = idx & 31;
        cpa(su + 49152 + 32768 + (u32)(c * 512 + q * 16), xb + (size_t)c * 32768 + q * 4);
    }
    cpcommit();

    int wm = (w >> 2) * 48, wn = (w & 3) * 32;
    int rA = ((l >> 3) & 1) * 8 + (l & 7);
    int ksel = ((l >> 4) & 1) * 16;

    for (int nc = 0; nc < 4; nc++) {
        u32 bo = su + 49152 + (u32)(nc & 1) * 65536;
        if (nc < 3) {
            u32 bn = su + 49152 + (u32)((nc + 1) & 1) * 65536;
            int n1 = (nc + 1) * 128;
            #pragma unroll
            for (int it = 0; it < 4; it++) {
                int idx = it * 512 + tid;
                int c = idx >> 5, q = idx & 31;
                cpa(bn + 32768 + (u32)(c * 512 + q * 16),
                    xb + (size_t)c * 32768 + n1 + q * 4);
            }
            cpcommit();
            cpwait<1>();
        } else {
            cpwait<0>();
        }
        __syncthreads();
        float* stage = (float*)(sm + (bo - su) + 32768);
        #pragma unroll
        for (int it = 0; it < 8; it++) {           // transpose+convert -> B [n][c]
            int idx = it * 512 + tid;
            int cp2 = idx >> 7, n = idx & 127;
            float a0 = stage[(cp2 * 2) * 128 + n];
            float a1 = stage[(cp2 * 2 + 1) * 128 + n];
            u32 u0 = __float_as_uint(a0), u1 = __float_as_uint(a1);
            u32 off = swz(n, cp2 * 4);
            *(u32*)(sm + (bo - su) + off) = __byte_perm(u0, u1, 0x7632);
            *(u32*)(sm + (bo - su) + 16384 + off) =
                packlo(a0 - __uint_as_float(u0 & 0xFFFF0000u),
                       a1 - __uint_as_float(u1 & 0xFFFF0000u));
        }
        __syncthreads();

        float acc[3][4][4];
        #pragma unroll
        for (int mi = 0; mi < 3; mi++)
            #pragma unroll
            for (int ni = 0; ni < 4; ni++)
                #pragma unroll
                for (int j = 0; j < 4; j++) acc[mi][ni][j] = 0.0f;

        #pragma unroll
        for (int s = 0; s < 4; s++) {
            int kb = s * 32 + ksel;
            u32 ah[3][4], al[3][4];
            #pragma unroll
            for (int mi = 0; mi < 3; mi++) {
                ldsm4(ah[mi], su + swz(wm + mi * 16 + rA, kb));
                ldsm4(al[mi], su + 24576 + swz(wm + mi * 16 + rA, kb));
            }
            #pragma unroll
            for (int g4 = 0; g4 < 2; g4++) {
                u32 bh[4], bl[4];
                ldsm4(bh, bo + swz(wn + g4 * 16 + rA, kb));
                ldsm4(bl, bo + 16384 + swz(wn + g4 * 16 + rA, kb));
                #pragma unroll
                for (int mi = 0; mi < 3; mi++)
                    #pragma unroll
                    for (int o = 0; o < 2; o++) {
                        int ni = g4 * 2 + o;
                        mma_bf(acc[mi][ni], ah[mi], bh[o], bh[o + 2]);
                        mma_bf(acc[mi][ni], al[mi], bh[o], bh[o + 2]);
                        mma_bf(acc[mi][ni], ah[mi], bl[o], bl[o + 2]);
                    }
            }
        }

        int n0 = nc * 128;
        #pragma unroll
        for (int mi = 0; mi < 3; mi++) {
            int mb = wm + mi * 16;
            int reg = mb >> 6;
            int o = (mb & 63) + (l >> 2);
            size_t base = (size_t)b * BELEM + (size_t)o * 32768 + (size_t)t * 512;
            #pragma unroll
            for (int ni = 0; ni < 4; ni++) {
                int col = n0 + wn + ni * 8 + 2 * (l & 3);
                float* d = acc[mi][ni];
                size_t o0 = base + col, o1 = o0 + (size_t)8 * 32768;
                if (reg == 0) {            // U1 -> A half 0
                    store_hl(g_Ah, g_Al, o0, d[0], d[1]);
                    store_hl(g_Ah, g_Al, o1, d[2], d[3]);
                } else if (reg == 1) {     // U2 -> A half 1
                    store_hl(g_Ah, g_Al, UOFF + o0, d[0], d[1]);
                    store_hl(g_Ah, g_Al, UOFF + o1, d[2], d[3]);
                } else {                   // U0 -> out
                    float2 v0 = { d[0], d[1] }, v1 = { d[2], d[3] };
                    *(float2*)&out[o0] = v0;
                    *(float2*)&out[o1] = v1;
                }
            }
        }
    }
}

// ---------------------------------------------------------------------------
// k_gg (256 thr, 2 CTAs/SM, 3-stage, bf16 3-product) — generic GEMM:
//  mode 0: La2 = La @ La          (A=La hl, B=LaT hl, K=512, out -> B half1 hl)
//  mode 1: out += [U1|U2] @ [La|La2]^T  (K=1024, dual-source by kc>=16)
// Stage (32KB): A 16KB (128B rows: [hi k32 | lo k32]), B 16KB same, +16384.
// warps: 8 = 2 m-warps (64 rows) x 4 n-warps (32 cols)
// ---------------------------------------------------------------------------
__device__ __forceinline__ void load_chunk(u32 sb, const u16* Ah, const u16* Al,
                                           const u16* Bh, const u16* Bl,
                                           int k0, int tid) {
    #pragma unroll
    for (int it = 0; it < 8; it++) {
        int idx = it * 256 + tid;
        int tile = idx >> 10;                        // 0=A, 1=B
        int r = (idx >> 3) & 127, c = idx & 7;
        int lo = c >> 2;
        const u16* base = tile ? (lo ? Bl : Bh) : (lo ? Al : Ah);
        const u16* g = base + (size_t)r * 512 + k0 + (c & 3) * 8;
        cpa(sb + tile * 16384 + swz(r, c * 16), g);
    }
    cpcommit();
}

__global__ __launch_bounds__(256, 2)
void k_gg(float* __restrict__ out, int mode) {
    extern __shared__ char sm[];
    int tid = threadIdx.x, w = tid >> 5, l = tid & 31;
    int blk = blockIdx.x;
    int b, m0, q0, NCH;
    const u16 *Ah, *Al, *Bh, *Bl;
    if (mode == 0) {
        b = blk >> 4; m0 = ((blk >> 2) & 3) * 128; q0 = (blk & 3) * 128; NCH = 16;
        Ah = g_Bh  + (size_t)b * LAELEM + (size_t)m0 * 512;
        Al = g_Bl  + (size_t)b * LAELEM + (size_t)m0 * 512;
        Bh = g_LaTh + (size_t)b * LAELEM + (size_t)q0 * 512;
        Bl = g_LaTl + (size_t)b * LAELEM + (size_t)q0 * 512;
    } else {
        b = blk >> 7; m0 = ((blk >> 2) & 31) * 128; q0 = (blk & 3) * 128; NCH = 32;
        Ah = g_Ah + (size_t)b * BELEM + (size_t)m0 * 512;
        Al = g_Al + (size_t)b * BELEM + (size_t)m0 * 512;
        Bh = g_Bh + (size_t)b * LAELEM + (size_t)q0 * 512;
        Bl = g_Bl + (size_t)b * LAELEM + (size_t)q0 * 512;
    }
    u32 su = s2u(sm);

    load_chunk(su,         Ah, Al, Bh, Bl, 0,  tid);   // chunk 0 (sel 0)
    load_chunk(su + 32768, Ah, Al, Bh, Bl, 32, tid);   // chunk 1 (sel 0)

    float acc[4][4][4];
    #pragma unroll
    for (int mi = 0; mi < 4; mi++)
        #pragma unroll
        for (int ni = 0; ni < 4; ni++)
            #pragma unroll
            for (int j = 0; j < 4; j++) acc[mi][ni][j] = 0.0f;

    int wm = (w >> 2) * 64, wn = (w & 3) * 32;
    int rA = ((l >> 3) & 1) * 8 + (l & 7);
    int ksel = ((l >> 4) & 1) * 16;

    for (int kc = 0; kc < NCH; kc++) {
        if (kc < NCH - 2) cpwait<1>(); else cpwait<0>();
        __syncthreads();
        int k2 = kc + 2;
        if (k2 < NCH) {
            size_t ao = (k2 >= 16) ? UOFF  : 0;
            size_t bo = (k2 >= 16) ? BOFF2 : 0;
            load_chunk(su + (u32)(k2 % 3) * 32768,
                       Ah + ao, Al + ao, Bh + bo, Bl + bo, (k2 & 15) * 32, tid);
        }
        u32 sb = su + (u32)(kc % 3) * 32768;
        #pragma unroll
        for (int s = 0; s < 2; s++) {
            int kb = s * 32 + ksel;
            u32 ah[4][4], al[4][4];
            #pragma unroll
            for (int mi = 0; mi < 4; mi++) {
                ldsm4(ah[mi], sb + swz(wm + mi * 16 + rA, kb));
                ldsm4(al[mi], sb + swz(wm + mi * 16 + rA, kb + 64));
            }
            #pragma unroll
            for (int g4 = 0; g4 < 2; g4++) {
                u32 bh[4], bl[4];
                ldsm4(bh, sb + 16384 + swz(wn + g4 * 16 + rA, kb));
                ldsm4(bl, sb + 16384 + swz(wn + g4 * 16 + rA, kb + 64));
                #pragma unroll
                for (int mi = 0; mi < 4; mi++)
                    #pragma unroll
                    for (int o = 0; o < 2; o++) {
                        int ni = g4 * 2 + o;
                        mma_bf(acc[mi][ni], ah[mi], bh[o], bh[o + 2]);
                        mma_bf(acc[mi][ni], al[mi], bh[o], bh[o + 2]);
                        mma_bf(acc[mi][ni], ah[mi], bl[o], bl[o + 2]);
                    }
            }
        }
    }

    #pragma unroll
    for (int mi = 0; mi < 4; mi++)
        #pragma unroll
        for (int ni = 0; ni < 4; ni++) {
            int row = m0 + wm + mi * 16 + (l >> 2);
            int col = q0 + wn + ni * 8 + 2 * (l & 3);
            float* d = acc[mi][ni];
            if (mode == 0) {               // La2 -> B half 1 (bf16 hl)
                size_t o0 = BOFF2 + (size_t)b * LAELEM + (size_t)row * 512 + col;
                size_t o1 = o0 + 8 * 512;
                store_hl(g_Bh, g_Bl, o0, d[0], d[1]);
                store_hl(g_Bh, g_Bl, o1, d[2], d[3]);
            } else {                       // out += acc
                size_t o0 = (size_t)b * BELEM + (size_t)row * 512 + col;
                size_t o1 = o0 + 8 * 512;
                float2 c0 = *(const float2*)&out[o0];
                float2 c1 = *(const float2*)&out[o1];
                float2 v0 = { d[0] + c0.x, d[1] + c0.y };
                float2 v1 = { d[2] + c1.x, d[3] + c1.y };
                *(float2*)&out[o0] = v0;
                *(float2*)&out[o1] = v1;
            }
        }
}

// ---------------------------------------------------------------------------
extern "C" void kernel_launch(void* const* d_in, const int* in_sizes, int n_in,
                              void* d_out, int out_size) {
    const float* x  = (const float*)d_in[0];
    const float* La = (const float*)d_in[1];
    const float* W  = (const float*)d_in[2];
    float* out = (float*)d_out;
    (void)in_sizes; (void)n_in; (void)out_size;

    cudaFuncSetAttribute(k_mix, cudaFuncAttributeMaxDynamicSharedMemorySize, 180224);
    cudaFuncSetAttribute(k_gg,  cudaFuncAttributeMaxDynamicSharedMemorySize, 98304);

    k_prep<<<4096, 256>>>(La);                        // La -> B half0 (hl)
    k_trans<<<dim3(16, 16, 16), dim3(32, 8)>>>(La);   // La^T (hl)
    k_wstk<<<48, 256>>>(W);
    k_gg<<<256, 256, 98304>>>(out, 0);                // La2 -> B half1
    k_mix<<<1024, 512, 180224>>>(x, out);             // U0->out, U1/U2 -> A halves
    k_gg<<<2048, 256, 98304>>>(out, 1);               // out += [U1|U2]@[La|La2]^T
}

// round 17
// speedup vs baseline: 1.4632x; 1.2987x over previous
#include <cuda_runtime.h>
#include <cuda_bf16.h>
#include <cuda_fp16.h>
#include <cstdint>

// Shapes: x[16,64,64,512], La[16,512,512], W[64,192]; out[16,64,64,512]
#define BELEM 2097152            // 64*64*512 per batch (row=o*64+t, col=n)
#define LAELEM 262144            // 512*512

typedef unsigned short u16;
typedef unsigned int u32;

__device__ __align__(16) float g_U1[(size_t)16 * BELEM];
__device__ __align__(16) u16   g_U2h[(size_t)16 * BELEM];   // fp16 hi
__device__ __align__(16) u16   g_U2l[(size_t)16 * BELEM];   // fp16 lo
__device__ __align__(16) u16   g_Ph [(size_t)16 * BELEM];   // fp16 hi
__device__ __align__(16) u16   g_Pl [(size_t)16 * BELEM];   // fp16 lo
__device__ __align__(16) u16   g_Laf[(size_t)16 * LAELEM];  // fp16 single
__device__ __align__(16) u16   g_Wsh[192 * 64];             // bf16 hi (mix)
__device__ __align__(16) u16   g_Wsl[192 * 64];             // bf16 lo (mix)

// ---------------------------------------------------------------------------
__device__ __forceinline__ u32 s2u(const void* p) {
    u32 a;
    asm("{ .reg .u64 t; cvta.to.shared.u64 t, %1; cvt.u32.u64 %0, t; }" : "=r"(a) : "l"(p));
    return a;
}
__device__ __forceinline__ u32 swz(int row, int kb) {       // 128B rows
    return (u32)(row * 128 + (kb ^ ((row & 7) << 4)));
}
// B layout: two 64B logical rows packed per 128B physical row, 4-phase XOR on
// the physical row. For any ldmatrix 8x8, the 8 lanes hit 8 distinct 16B banks.
__device__ __forceinline__ u32 swzB2(int r, int kb) {
    return (u32)((r >> 1) * 128 + (r & 1) * 64 + (kb ^ (((r >> 1) & 3) << 4)));
}
__device__ __forceinline__ void cpa(u32 s, const void* g) {
    asm volatile("cp.async.cg.shared.global [%0], [%1], 16;" :: "r"(s), "l"(g));
}
__device__ __forceinline__ void cpcommit() {
    asm volatile("cp.async.commit_group;" ::: "memory");
}
template<int N> __device__ __forceinline__ void cpwait() {
    asm volatile("cp.async.wait_group %0;" :: "n"(N) : "memory");
}
__device__ __forceinline__ void ldsm4(u32* r, u32 a) {
    asm volatile("ldmatrix.sync.aligned.m8n8.x4.shared.b16 {%0,%1,%2,%3}, [%4];"
        : "=r"(r[0]), "=r"(r[1]), "=r"(r[2]), "=r"(r[3]) : "r"(a));
}
__device__ __forceinline__ void mma_bf(float* d, const u32* a, u32 b0, u32 b1) {
    asm volatile("mma.sync.aligned.m16n8k16.row.col.f32.bf16.bf16.f32 "
        "{%0,%1,%2,%3}, {%4,%5,%6,%7}, {%8,%9}, {%0,%1,%2,%3};"
        : "+f"(d[0]), "+f"(d[1]), "+f"(d[2]), "+f"(d[3])
        : "r"(a[0]), "r"(a[1]), "r"(a[2]), "r"(a[3]), "r"(b0), "r"(b1));
}
__device__ __forceinline__ void mma_fp(float* d, const u32* a, u32 b0, u32 b1) {
    asm volatile("mma.sync.aligned.m16n8k16.row.col.f32.f16.f16.f32 "
        "{%0,%1,%2,%3}, {%4,%5,%6,%7}, {%8,%9}, {%0,%1,%2,%3};"
        : "+f"(d[0]), "+f"(d[1]), "+f"(d[2]), "+f"(d[3])
        : "r"(a[0]), "r"(a[1]), "r"(a[2]), "r"(a[3]), "r"(b0), "r"(b1));
}
__device__ __forceinline__ u32 packlo(float lx, float ly) {  // bf16x2 {ly|lx}
    u32 r;
    asm("cvt.rn.bf16x2.f32 %0, %1, %2;" : "=r"(r) : "f"(ly), "f"(lx));
    return r;
}
__device__ __forceinline__ u32 packh2(float lx, float ly) {  // fp16x2 {ly|lx}
    __half h0 = __float2half_rn(lx), h1 = __float2half_rn(ly);
    return ((u32)__half_as_ushort(h1) << 16) | __half_as_ushort(h0);
}
// fp16 hi/lo split store: hi = RN fp16, lo = RN fp16 of residual
__device__ __forceinline__ void store_hl16(u16* H, u16* L, size_t off, float v0, float v1) {
    __half h0 = __float2half_rn(v0), h1 = __float2half_rn(v1);
    *(u32*)(H + off) = ((u32)__half_as_ushort(h1) << 16) | __half_as_ushort(h0);
    float r0 = v0 - __half2float(h0);
    float r1 = v1 - __half2float(h1);
    *(u32*)(L + off) = packh2(r0, r1);
}

// ---------------------------------------------------------------------------
// k_prep: La fp32 -> fp16 single
// ---------------------------------------------------------------------------
__global__ void k_prep(const float* __restrict__ La) {
    int i = blockIdx.x * blockDim.x + threadIdx.x;   // float4 index
    float4 v = __ldg((const float4*)La + i);
    uint2 h = { packh2(v.x, v.y), packh2(v.z, v.w) };
    ((uint2*)g_Laf)[i] = h;
}

__global__ void k_wstk(const float* __restrict__ W) {
    int i = blockIdx.x * blockDim.x + threadIdx.x;
    if (i >= 192 * 64) return;
    int r = i >> 6, c = i & 63;
    int o = r & 63, reg = r >> 6;
    float v = (reg == 0) ? W[o * 192 + 3 * c + 1]
            : (reg == 1) ? 2.0f * W[o * 192 + 3 * c + 2]
            : W[o * 192 + 3 * c] - W[o * 192 + 3 * c + 2];
    u32 u = __float_as_uint(v);
    g_Wsh[i] = (u16)(u >> 16);
    float res = v - __uint_as_float(u & 0xFFFF0000u);
    __nv_bfloat16 rb = __float2bfloat16(res);
    g_Wsl[i] = *(u16*)&rb;
}

// ---------------------------------------------------------------------------
// k_mix (512 thr, 3xbf16 core, double-buffered staging): per (b,t):
// A=Wstk[192][64] h/l bf16, B=X^T [128 n][64 c] h/l bf16.
// Rows 0-63 -> U1 fp32, 64-127 -> U2 fp16 h/l, 128-191 -> out fp32.
// smem: Wh 0 (24K), Wl 24576; buf k at 49152+k*65536:
//       Bh +0 (16K), Bl +16384, stage +32768 (32K fp32). total 180224
// ---------------------------------------------------------------------------
__global__ __launch_bounds__(512, 1)
void k_mix(const float* __restrict__ x, float* __restrict__ out) {
    extern __shared__ char sm[];
    int tid = threadIdx.x, w = tid >> 5, l = tid & 31;
    int b = blockIdx.x >> 6, t = blockIdx.x & 63;
    u32 su = s2u(sm);
    const float* xb = x + (size_t)b * BELEM + (size_t)t * 512;

    #pragma unroll
    for (int it = 0; it < 6; it++) {               // W: 3072 16B chunks
        int idx = it * 512 + tid;
        int half = idx >= 1536;
        int rem = idx - half * 1536;
        int r = rem >> 3, c = rem & 7;
        const u16* g = (half ? g_Wsl : g_Wsh) + r * 64 + c * 8;
        cpa(su + half * 24576 + swz(r, c * 16), g);
    }
    cpcommit();

    #pragma unroll
    for (int it = 0; it < 4; it++) {               // stage chunk 0
        int idx = it * 512 + tid;
        int c = idx >> 5, q = idx & 31;
        cpa(su + 49152 + 32768 + (u32)(c * 512 + q * 16), xb + (size_t)c * 32768 + q * 4);
    }
    cpcommit();

    int wm = (w >> 2) * 48, wn = (w & 3) * 32;
    int rA = ((l >> 3) & 1) * 8 + (l & 7);
    int ksel = ((l >> 4) & 1) * 16;

    for (int nc = 0; nc < 4; nc++) {
        u32 bo = su + 49152 + (u32)(nc & 1) * 65536;
        if (nc < 3) {
            u32 bn = su + 49152 + (u32)((nc + 1) & 1) * 65536;
            int n1 = (nc + 1) * 128;
            #pragma unroll
            for (int it = 0; it < 4; it++) {
                int idx = it * 512 + tid;
                int c = idx >> 5, q = idx & 31;
                cpa(bn + 32768 + (u32)(c * 512 + q * 16),
                    xb + (size_t)c * 32768 + n1 + q * 4);
            }
            cpcommit();
            cpwait<1>();
        } else {
            cpwait<0>();
        }
        __syncthreads();
        float* stage = (float*)(sm + (bo - su) + 32768);
        #pragma unroll
        for (int it = 0; it < 8; it++) {           // transpose+convert -> B [n][c]
            int idx = it * 512 + tid;
            int cp2 = idx >> 7, n = idx & 127;
            float a0 = stage[(cp2 * 2) * 128 + n];
            float a1 = stage[(cp2 * 2 + 1) * 128 + n];
            u32 u0 = __float_as_uint(a0), u1 = __float_as_uint(a1);
            u32 off = swz(n, cp2 * 4);
            *(u32*)(sm + (bo - su) + off) = __byte_perm(u0, u1, 0x7632);
            *(u32*)(sm + (bo - su) + 16384 + off) =
                packlo(a0 - __uint_as_float(u0 & 0xFFFF0000u),
                       a1 - __uint_as_float(u1 & 0xFFFF0000u));
        }
        __syncthreads();

        float acc[3][4][4];
        #pragma unroll
        for (int mi = 0; mi < 3; mi++)
            #pragma unroll
            for (int ni = 0; ni < 4; ni++)
                #pragma unroll
                for (int j = 0; j < 4; j++) acc[mi][ni][j] = 0.0f;

        #pragma unroll
        for (int s = 0; s < 4; s++) {
            int kb = s * 32 + ksel;
            u32 ah[3][4], al[3][4];
            #pragma unroll
            for (int mi = 0; mi < 3; mi++) {
                ldsm4(ah[mi], su + swz(wm + mi * 16 + rA, kb));
                ldsm4(al[mi], su + 24576 + swz(wm + mi * 16 + rA, kb));
            }
            #pragma unroll
            for (int g4 = 0; g4 < 2; g4++) {
                u32 bh[4], bl[4];
                ldsm4(bh, bo + swz(wn + g4 * 16 + rA, kb));
                ldsm4(bl, bo + 16384 + swz(wn + g4 * 16 + rA, kb));
                #pragma unroll
                for (int mi = 0; mi < 3; mi++)
                    #pragma unroll
                    for (int o = 0; o < 2; o++) {
                        int ni = g4 * 2 + o;
                        mma_bf(acc[mi][ni], ah[mi], bh[o], bh[o + 2]);
                        mma_bf(acc[mi][ni], al[mi], bh[o], bh[o + 2]);
                        mma_bf(acc[mi][ni], ah[mi], bl[o], bl[o + 2]);
                    }
            }
        }

        int n0 = nc * 128;
        #pragma unroll
        for (int mi = 0; mi < 3; mi++) {
            int mb = wm + mi * 16;
            int reg = mb >> 6;
            int o = (mb & 63) + (l >> 2);
            size_t base = (size_t)b * BELEM + (size_t)o * 32768 + (size_t)t * 512;
            #pragma unroll
            for (int ni = 0; ni < 4; ni++) {
                int col = n0 + wn + ni * 8 + 2 * (l & 3);
                float* d = acc[mi][ni];
                size_t o0 = base + col, o1 = o0 + (size_t)8 * 32768;
                if (reg == 0) {
                    float2 v0 = { d[0], d[1] }, v1 = { d[2], d[3] };
                    *(float2*)&g_U1[o0] = v0;
                    *(float2*)&g_U1[o1] = v1;
                } else if (reg == 1) {
                    store_hl16(g_U2h, g_U2l, o0, d[0], d[1]);
                    store_hl16(g_U2h, g_U2l, o1, d[2], d[3]);
                } else {
                    float2 v0 = { d[0], d[1] }, v1 = { d[2], d[3] };
                    *(float2*)&out[o0] = v0;
                    *(float2*)&out[o1] = v1;
                }
            }
        }
    }
}

// ---------------------------------------------------------------------------
// k_gemm (256 thr, 2 CTAs/SM, 4-stage, fp16 2-product, conflict-free B):
// pass0: P = U1 + U2@La^T; pass1: out += P@La^T. CTA tile 128x128,
// K=512 in 16 chunks of 32. Stage (24KB): A 16KB (128B rows: [hi k32|lo k32]),
// B 8KB (paired-64B rows via swzB2, fp16 single). 4 stages = 96KB.
// warps: 8 = 2 m-warps (64 rows) x 4 n-warps (32 cols)
// ---------------------------------------------------------------------------
__device__ __forceinline__ void load_chunk(u32 sb, const u16* Ah, const u16* Al,
                                           const u16* Bf, int kc, int tid) {
    int k0 = kc * 32;
    #pragma unroll
    for (int it = 0; it < 6; it++) {
        int idx = it * 256 + tid;
        if (idx < 1024) {                            // A: 128 rows x 8 chunks
            int r = (idx >> 3) & 127, c = idx & 7;
            int lo = c >> 2;
            const u16* g = (lo ? Al : Ah) + (size_t)r * 512 + k0 + (c & 3) * 8;
            cpa(sb + swz(r, c * 16), g);
        } else {                                     // B: 128 rows x 4 chunks
            int rem = idx - 1024;
            int r = rem >> 2, c = rem & 3;
            const u16* g = Bf + (size_t)r * 512 + k0 + c * 8;
            cpa(sb + 16384 + swzB2(r, c * 16), g);
        }
    }
    cpcommit();
}

__global__ __launch_bounds__(256, 2)
void k_gemm(float* __restrict__ out, int pass) {
    extern __shared__ char sm[];
    int tid = threadIdx.x, w = tid >> 5, l = tid & 31;
    int blk = blockIdx.x;
    int b = blk >> 7, mt = (blk >> 2) & 31, qt = blk & 3;
    int m0 = mt * 128, q0 = qt * 128;

    const u16* A0 = (pass ? g_Ph : g_U2h) + (size_t)b * BELEM + (size_t)m0 * 512;
    const u16* A1 = (pass ? g_Pl : g_U2l) + (size_t)b * BELEM + (size_t)m0 * 512;
    const u16* Bf = g_Laf + (size_t)b * LAELEM + (size_t)q0 * 512;
    u32 su = s2u(sm);

    load_chunk(su,         A0, A1, Bf, 0, tid);
    load_chunk(su + 24576, A0, A1, Bf, 1, tid);
    load_chunk(su + 49152, A0, A1, Bf, 2, tid);

    float acc[4][4][4];
    #pragma unroll
    for (int mi = 0; mi < 4; mi++)
        #pragma unroll
        for (int ni = 0; ni < 4; ni++)
            #pragma unroll
            for (int j = 0; j < 4; j++) acc[mi][ni][j] = 0.0f;

    int wm = (w >> 2) * 64, wn = (w & 3) * 32;
    int rA = ((l >> 3) & 1) * 8 + (l & 7);
    int ksel = ((l >> 4) & 1) * 16;

    for (int kc = 0; kc < 16; kc++) {
        if (kc <= 13) cpwait<2>();
        else if (kc == 14) cpwait<1>();
        else cpwait<0>();
        __syncthreads();
        if (kc + 3 < 16)
            load_chunk(su + (u32)((kc + 3) & 3) * 24576, A0, A1, Bf, kc + 3, tid);
        u32 sb = su + (u32)(kc & 3) * 24576;
        #pragma unroll
        for (int s = 0; s < 2; s++) {
            int kb = s * 32 + ksel;
            u32 ah[4][4], al[4][4];
            #pragma unroll
            for (int mi = 0; mi < 4; mi++) {
                ldsm4(ah[mi], sb + swz(wm + mi * 16 + rA, kb));
                ldsm4(al[mi], sb + swz(wm + mi * 16 + rA, kb + 64));
            }
            #pragma unroll
            for (int g4 = 0; g4 < 2; g4++) {
                u32 bh[4];
                ldsm4(bh, sb + 16384 + swzB2(wn + g4 * 16 + rA, kb));
                #pragma unroll
                for (int mi = 0; mi < 4; mi++)
                    #pragma unroll
                    for (int o = 0; o < 2; o++) {
                        int ni = g4 * 2 + o;
                        mma_fp(acc[mi][ni], ah[mi], bh[o], bh[o + 2]);
                        mma_fp(acc[mi][ni], al[mi], bh[o], bh[o + 2]);
                    }
            }
        }
    }

    #pragma unroll
    for (int mi = 0; mi < 4; mi++)
        #pragma unroll
        for (int ni = 0; ni < 4; ni++) {
            int row = m0 + wm + mi * 16 + (l >> 2);
            int col = q0 + wn + ni * 8 + 2 * (l & 3);
            size_t o0 = (size_t)b * BELEM + (size_t)row * 512 + col;
            size_t o1 = o0 + 8 * 512;
            float* d = acc[mi][ni];
            if (pass == 0) {
                float2 c0 = *(const float2*)&g_U1[o0];
                float2 c1 = *(const float2*)&g_U1[o1];
                store_hl16(g_Ph, g_Pl, o0, d[0] + c0.x, d[1] + c0.y);
                store_hl16(g_Ph, g_Pl, o1, d[2] + c1.x, d[3] + c1.y);
            } else {
                float2 c0 = *(const float2*)&out[o0];
                float2 c1 = *(const float2*)&out[o1];
                float2 v0 = { d[0] + c0.x, d[1] + c0.y };
                float2 v1 = { d[2] + c1.x, d[3] + c1.y };
                *(float2*)&out[o0] = v0;
                *(float2*)&out[o1] = v1;
            }
        }
}

// ---------------------------------------------------------------------------
extern "C" void kernel_launch(void* const* d_in, const int* in_sizes, int n_in,
                              void* d_out, int out_size) {
    const float* x  = (const float*)d_in[0];
    const float* La = (const float*)d_in[1];
    const float* W  = (const float*)d_in[2];
    float* out = (float*)d_out;
    (void)in_sizes; (void)n_in; (void)out_size;

    cudaFuncSetAttribute(k_mix,  cudaFuncAttributeMaxDynamicSharedMemorySize, 180224);
    cudaFuncSetAttribute(k_gemm, cudaFuncAttributeMaxDynamicSharedMemorySize, 98304);

    k_prep<<<4096, 256>>>(La);
    k_wstk<<<48, 256>>>(W);
    k_mix<<<1024, 512, 180224>>>(x, out);
    k_gemm<<<2048, 256, 98304>>>(out, 0);
    k_gemm<<<2048, 256, 98304>>>(out, 1);
}